// round 1
// baseline (speedup 1.0000x reference)
#include <cuda_runtime.h>

// WaveletLayer: fused db2 DWT -> elementwise scale -> inverse DWT -> ReLU
// x: (4096, 4096) f32, kernel: (4096, 2049) f32, out: (4096, 4096) f32
//
// Per row b:
//   xe = symmetric pad(3) of x[b]
//   cA[m] = l3*xe[2m+1] + l2*xe[2m+2] + l1*xe[2m+3] + l0*xe[2m+4], m in [0,2049)
//   cD[m] = same with hi filter
//   A[m] = cA[m]*K[b][m], D[m] = cD[m]*K[b][m]
//   y[2m0]   = l1*A[m0] + l3*A[m0+1] + h1*D[m0] + h3*D[m0+1]
//   y[2m0+1] = l0*A[m0] + l2*A[m0+1] + h0*D[m0] + h2*D[m0+1]
//   out = relu(y)

#define ROWS 4096
#define NCOL 4096
#define LOUT 2049
#define NT 256

__global__ __launch_bounds__(NT) void wavelet_fused_kernel(
    const float* __restrict__ x,
    const float* __restrict__ kern,
    float* __restrict__ out)
{
    __shared__ float sxe[NCOL + 6];

    const int row = blockIdx.x;
    const float* xr = x + (size_t)row * NCOL;

    // Stage symmetric-padded row: sxe[i] = x[sym(i-3)]
    for (int i = threadIdx.x; i < NCOL + 6; i += NT) {
        int t = i - 3;
        if (t < 0) t = -t - 1;              // t=-1 -> 0, -2 -> 1, -3 -> 2
        else if (t >= NCOL) t = 2 * NCOL - 1 - t;  // t=N -> N-1, etc.
        sxe[i] = xr[t];
    }
    __syncthreads();

    const float l0 = -0.12940952255126037f;
    const float l1 =  0.22414386804185735f;
    const float l2 =  0.8365163037378079f;
    const float l3 =  0.48296291314453416f;
    const float h0 = -0.48296291314453416f;
    const float h1 =  0.8365163037378079f;
    const float h2 = -0.22414386804185735f;
    const float h3 = -0.12940952255126037f;

    const float* kr   = kern + (size_t)row * LOUT;
    float*       outr = out  + (size_t)row * NCOL;

    for (int m0 = threadIdx.x; m0 < NCOL / 2; m0 += NT) {
        const int base = 2 * m0;
        float s1 = sxe[base + 1];
        float s2 = sxe[base + 2];
        float s3 = sxe[base + 3];
        float s4 = sxe[base + 4];
        float s5 = sxe[base + 5];
        float s6 = sxe[base + 6];

        float A0 = l3 * s1 + l2 * s2 + l1 * s3 + l0 * s4;
        float D0 = h3 * s1 + h2 * s2 + h1 * s3 + h0 * s4;
        float A1 = l3 * s3 + l2 * s4 + l1 * s5 + l0 * s6;
        float D1 = h3 * s3 + h2 * s4 + h1 * s5 + h0 * s6;

        float k0 = kr[m0];
        float k1 = kr[m0 + 1];
        A0 *= k0; D0 *= k0;
        A1 *= k1; D1 *= k1;

        float ye = l1 * A0 + l3 * A1 + h1 * D0 + h3 * D1;
        float yo = l0 * A0 + l2 * A1 + h0 * D0 + h2 * D1;

        float2 v = make_float2(fmaxf(ye, 0.0f), fmaxf(yo, 0.0f));
        *reinterpret_cast<float2*>(outr + base) = v;
    }
}

extern "C" void kernel_launch(void* const* d_in, const int* in_sizes, int n_in,
                              void* d_out, int out_size)
{
    const float* x    = (const float*)d_in[0];
    const float* kern = (const float*)d_in[1];
    float*       out  = (float*)d_out;

    wavelet_fused_kernel<<<ROWS, NT>>>(x, kern, out);
}

// round 2
// speedup vs baseline: 2.0603x; 2.0603x over previous
#include <cuda_runtime.h>

// WaveletLayer fused: db2 DWT -> scale by kernel -> inverse DWT -> ReLU
// x: (4096,4096) f32, kernel: (4096,2049) f32, out: (4096,4096) f32
//
// Closed form per row (xe = symmetric pad(3), K = kernel row):
//   cA[m] = l3*xe[2m+1]+l2*xe[2m+2]+l1*xe[2m+3]+l0*xe[2m+4]   (cD with hi taps)
//   A[m]=cA[m]*K[m], D[m]=cD[m]*K[m]
//   y[2m]   = l1*A[m]+l3*A[m+1]+h1*D[m]+h3*D[m+1]
//   y[2m+1] = l0*A[m]+l2*A[m+1]+h0*D[m]+h2*D[m+1]
//   out = relu(y)
//
// R2 design: no shared memory, no syncs. Each thread computes 4 output pairs
// (8 contiguous floats). x window x[base-2..base+9] via 4 overlapping LDG.128
// (L1 absorbs the 2x overlap), K[m0..m0+4] via 5 scalar loads, A/D computed
// once and reused across adjacent pairs, two STG.128 out.

#define NCOL 4096
#define LOUT 2049
#define NT   256

__device__ __forceinline__ int symidx(int t) {
    if (t < 0) return -t - 1;
    if (t >= NCOL) return 2 * NCOL - 1 - t;
    return t;
}

__global__ __launch_bounds__(NT) void wavelet_fused_kernel(
    const float* __restrict__ x,
    const float* __restrict__ kern,
    float* __restrict__ out)
{
    const int row  = blockIdx.y;
    const int m0   = blockIdx.x * (NT * 4) + threadIdx.x * 4;   // first pair index
    const int base = 2 * m0;                                    // output col of first pair

    const float* xr = x + (size_t)row * NCOL;

    // s[k] = xe[base + 1 + k] = x_sym(base - 2 + k), k = 0..11
    float s[12];
    if (base >= 4 && base + 11 <= NCOL - 1) {
        const float4* x4 = reinterpret_cast<const float4*>(xr);
        const int q = base >> 2;
        float4 q0 = x4[q - 1];
        float4 q1 = x4[q];
        float4 q2 = x4[q + 1];
        float4 q3 = x4[q + 2];
        s[0] = q0.z;  s[1] = q0.w;
        s[2] = q1.x;  s[3] = q1.y;  s[4] = q1.z;  s[5] = q1.w;
        s[6] = q2.x;  s[7] = q2.y;  s[8] = q2.z;  s[9] = q2.w;
        s[10] = q3.x; s[11] = q3.y;
    } else {
        #pragma unroll
        for (int k = 0; k < 12; k++)
            s[k] = xr[symidx(base - 2 + k)];
    }

    const float l0 = -0.12940952255126037f;
    const float l1 =  0.22414386804185735f;
    const float l2 =  0.8365163037378079f;
    const float l3 =  0.48296291314453416f;
    const float h0 = -0.48296291314453416f;
    const float h1 =  0.8365163037378079f;
    const float h2 = -0.22414386804185735f;
    const float h3 = -0.12940952255126037f;

    const float* kr = kern + (size_t)row * LOUT + m0;

    // A[m], D[m] for m = m0 .. m0+4 (local 0..4), window s[2m..2m+3]
    float A[5], D[5];
    #pragma unroll
    for (int m = 0; m < 5; m++) {
        float a = l3 * s[2 * m]     + l2 * s[2 * m + 1]
                + l1 * s[2 * m + 2] + l0 * s[2 * m + 3];
        float d = h3 * s[2 * m]     + h2 * s[2 * m + 1]
                + h1 * s[2 * m + 2] + h0 * s[2 * m + 3];
        float k = kr[m];
        A[m] = a * k;
        D[m] = d * k;
    }

    float r[8];
    #pragma unroll
    for (int j = 0; j < 4; j++) {
        float ye = l1 * A[j] + l3 * A[j + 1] + h1 * D[j] + h3 * D[j + 1];
        float yo = l0 * A[j] + l2 * A[j + 1] + h0 * D[j] + h2 * D[j + 1];
        r[2 * j]     = fmaxf(ye, 0.0f);
        r[2 * j + 1] = fmaxf(yo, 0.0f);
    }

    float4* out4 = reinterpret_cast<float4*>(out + (size_t)row * NCOL + base);
    out4[0] = make_float4(r[0], r[1], r[2], r[3]);
    out4[1] = make_float4(r[4], r[5], r[6], r[7]);
}

extern "C" void kernel_launch(void* const* d_in, const int* in_sizes, int n_in,
                              void* d_out, int out_size)
{
    const float* x    = (const float*)d_in[0];
    const float* kern = (const float*)d_in[1];
    float*       out  = (float*)d_out;

    dim3 grid(2, 4096);   // 2 blocks of 256 threads x 4 pairs = 2048 pairs/row
    wavelet_fused_kernel<<<grid, NT>>>(x, kern, out);
}

// round 3
// speedup vs baseline: 2.0671x; 1.0033x over previous
#include <cuda_runtime.h>

// WaveletLayer fused: db2 DWT -> scale -> inverse DWT -> ReLU
// x: (4096,4096) f32, kernel: (4096,2049) f32, out: (4096,4096) f32
//
// R3: minimize L1 wavefronts.
//  - x: 2 aligned LDG.128 per thread (exact coverage), halo via warp shuffle,
//    lanes 0/31 patch halo with scalar loads (with symmetric reflect at row ends).
//  - K: the 5-value window K[m0..m0+4] has block-uniform misalignment d=row&3;
//    covered by 2 aligned LDG.128 + uniform select.
//  - out: 2 STG.128 with .cs hint (write-once stream).

#define NCOL 4096
#define LOUT 2049
#define NT   256
#define FULL 0xffffffffu

__global__ __launch_bounds__(NT) void wavelet_fused_kernel(
    const float* __restrict__ x,
    const float* __restrict__ kern,
    float* __restrict__ out)
{
    const int row  = blockIdx.y;
    const int m0   = blockIdx.x * (NT * 4) + threadIdx.x * 4;  // first pair idx
    const int base = 2 * m0;                                    // first out col (mult of 8)
    const int lane = threadIdx.x & 31;

    const float* xr = x + (size_t)row * NCOL;

    // Core: x[base .. base+7], two aligned float4 loads
    const float4* x4 = reinterpret_cast<const float4*>(xr);
    const int q = base >> 2;
    float4 qa = x4[q];
    float4 qb = x4[q + 1];
    // c0..c7 = x[base..base+7]
    float c0 = qa.x, c1 = qa.y, c2 = qa.z, c3 = qa.w;
    float c4 = qb.x, c5 = qb.y, c6 = qb.z, c7 = qb.w;

    // Halo via shuffle: left = prev lane's c6,c7 ; right = next lane's c0,c1
    float hl0 = __shfl_up_sync(FULL, c6, 1);    // x[base-2]
    float hl1 = __shfl_up_sync(FULL, c7, 1);    // x[base-1]
    float hr0 = __shfl_down_sync(FULL, c0, 1);  // x[base+8]
    float hr1 = __shfl_down_sync(FULL, c1, 1);  // x[base+9]

    if (lane == 0) {
        if (base == 0) { hl0 = xr[1]; hl1 = xr[0]; }            // symmetric reflect
        else           { hl0 = xr[base - 2]; hl1 = xr[base - 1]; }
    }
    if (lane == 31) {
        if (base == NCOL - 8) { hr0 = xr[NCOL - 1]; hr1 = xr[NCOL - 2]; }  // reflect
        else                  { hr0 = xr[base + 8]; hr1 = xr[base + 9]; }
    }

    // s[k] = x_sym(base - 2 + k), k = 0..11
    float s0 = hl0, s1 = hl1;
    float s2 = c0, s3 = c1, s4 = c2, s5 = c3, s6 = c4, s7 = c5, s8 = c6, s9 = c7;
    float s10 = hr0, s11 = hr1;

    // K window K[m0 .. m0+4]: uniform misalignment d = row & 3
    const int w = LOUT * row + m0;
    const int d = w & 3;                 // uniform across block (= row & 3)
    const float4* kp = reinterpret_cast<const float4*>(kern + (w - d));
    float4 f0 = kp[0];
    float4 f1 = kp[1];
    float k0, k1, k2, k3, k4;
    if (d == 0)      { k0 = f0.x; k1 = f0.y; k2 = f0.z; k3 = f0.w; k4 = f1.x; }
    else if (d == 1) { k0 = f0.y; k1 = f0.z; k2 = f0.w; k3 = f1.x; k4 = f1.y; }
    else if (d == 2) { k0 = f0.z; k1 = f0.w; k2 = f1.x; k3 = f1.y; k4 = f1.z; }
    else             { k0 = f0.w; k1 = f1.x; k2 = f1.y; k3 = f1.z; k4 = f1.w; }

    const float l0 = -0.12940952255126037f;
    const float l1 =  0.22414386804185735f;
    const float l2 =  0.8365163037378079f;
    const float l3 =  0.48296291314453416f;
    const float h0 = -0.48296291314453416f;
    const float h1 =  0.8365163037378079f;
    const float h2 = -0.22414386804185735f;
    const float h3 = -0.12940952255126037f;

    // A[m], D[m] for 5 consecutive m, window s[2m..2m+3]
    float A0 = (l3 * s0 + l2 * s1 + l1 * s2  + l0 * s3)  * k0;
    float D0 = (h3 * s0 + h2 * s1 + h1 * s2  + h0 * s3)  * k0;
    float A1 = (l3 * s2 + l2 * s3 + l1 * s4  + l0 * s5)  * k1;
    float D1 = (h3 * s2 + h2 * s3 + h1 * s4  + h0 * s5)  * k1;
    float A2 = (l3 * s4 + l2 * s5 + l1 * s6  + l0 * s7)  * k2;
    float D2 = (h3 * s4 + h2 * s5 + h1 * s6  + h0 * s7)  * k2;
    float A3 = (l3 * s6 + l2 * s7 + l1 * s8  + l0 * s9)  * k3;
    float D3 = (h3 * s6 + h2 * s7 + h1 * s8  + h0 * s9)  * k3;
    float A4 = (l3 * s8 + l2 * s9 + l1 * s10 + l0 * s11) * k4;
    float D4 = (h3 * s8 + h2 * s9 + h1 * s10 + h0 * s11) * k4;

    float4 r0, r1;
    r0.x = fmaxf(l1 * A0 + l3 * A1 + h1 * D0 + h3 * D1, 0.0f);
    r0.y = fmaxf(l0 * A0 + l2 * A1 + h0 * D0 + h2 * D1, 0.0f);
    r0.z = fmaxf(l1 * A1 + l3 * A2 + h1 * D1 + h3 * D2, 0.0f);
    r0.w = fmaxf(l0 * A1 + l2 * A2 + h0 * D1 + h2 * D2, 0.0f);
    r1.x = fmaxf(l1 * A2 + l3 * A3 + h1 * D2 + h3 * D3, 0.0f);
    r1.y = fmaxf(l0 * A2 + l2 * A3 + h0 * D2 + h2 * D3, 0.0f);
    r1.z = fmaxf(l1 * A3 + l3 * A4 + h1 * D3 + h3 * D4, 0.0f);
    r1.w = fmaxf(l0 * A3 + l2 * A4 + h0 * D3 + h2 * D4, 0.0f);

    float4* o4 = reinterpret_cast<float4*>(out + (size_t)row * NCOL + base);
    __stcs(o4,     r0);
    __stcs(o4 + 1, r1);
}

extern "C" void kernel_launch(void* const* d_in, const int* in_sizes, int n_in,
                              void* d_out, int out_size)
{
    const float* x    = (const float*)d_in[0];
    const float* kern = (const float*)d_in[1];
    float*       out  = (float*)d_out;

    dim3 grid(2, 4096);   // 2 blocks x 256 threads x 4 pairs = 2048 pairs/row
    wavelet_fused_kernel<<<grid, NT>>>(x, kern, out);
}